// round 6
// baseline (speedup 1.0000x reference)
#include <cuda_runtime.h>
#include <cuda_bf16.h>
#include <math.h>
#include <stdint.h>

#define BB 64
#define TT 4096
#define DD 90
#define KK 32
#define CC 32            // chunks per batch
#define CHUNK 128        // TT / CC
#define WARM 32          // burn-in steps (Birkhoff contraction <=0.762^32 ~ 1.6e-4)
#define NBLK (BB * CC / 4)       // 512 scan blocks (4 chains per warp)
#define NEB  (BB * TT / 128)     // 2048 emission blocks
#define LOG2PI_F 1.8378770664093453f
#define FULLMASK 0xffffffffu

// ---- scratch (__device__ globals; no allocations allowed) ----
__device__ __align__(16) float g_eexp[BB * TT * KK];     // exp(em - emax)
__device__ __align__(16) uint2 g_Wb[12 * 4 * 32];        // bf16 B-fragment table
__device__ __align__(16) float g_bias[KK];
__device__ float g_pi[KK];
__device__ float g_expA[KK * KK];
__device__ __align__(16) float g_partial2[BB * CC];      // per-chunk log factors
__device__ __align__(16) float g_emaxpart[NEB];          // per-emis-block emax sums
__device__ unsigned g_ctr;                                // scan completion counter

__device__ __forceinline__ float warpMax(float v) {
#pragma unroll
    for (int o = 16; o > 0; o >>= 1) v = fmaxf(v, __shfl_xor_sync(FULLMASK, v, o));
    return v;
}
__device__ __forceinline__ float warpSum(float v) {
#pragma unroll
    for (int o = 16; o > 0; o >>= 1) v += __shfl_xor_sync(FULLMASK, v, o);
    return v;
}
__device__ __forceinline__ uint32_t packbf2(float lo, float hi) {
    __nv_bfloat162 h = __floats2bfloat162_rn(lo, hi);
    return *reinterpret_cast<uint32_t*>(&h);
}
__device__ __forceinline__ void mma_bf16(float& d0, float& d1, float& d2, float& d3,
                                         uint32_t a0, uint32_t a1, uint32_t a2, uint32_t a3,
                                         uint32_t b0, uint32_t b1) {
    asm volatile("mma.sync.aligned.m16n8k16.row.col.f32.bf16.bf16.f32 "
                 "{%0,%1,%2,%3},{%4,%5,%6,%7},{%8,%9},{%0,%1,%2,%3};"
                 : "+f"(d0), "+f"(d1), "+f"(d2), "+f"(d3)
                 : "r"(a0), "r"(a1), "r"(a2), "r"(a3), "r"(b0), "r"(b1));
}

// ---- packed f32x2 helpers (Blackwell) ----
__device__ __forceinline__ uint64_t pack2(float lo, float hi) {
    uint64_t r;
    asm("mov.b64 %0, {%1, %2};" : "=l"(r)
        : "r"(__float_as_uint(lo)), "r"(__float_as_uint(hi)));
    return r;
}
__device__ __forceinline__ float2 unpack2(uint64_t v) {
    uint32_t lo, hi;
    asm("mov.b64 {%0, %1}, %2;" : "=r"(lo), "=r"(hi) : "l"(v));
    return make_float2(__uint_as_float(lo), __uint_as_float(hi));
}
__device__ __forceinline__ uint64_t mul2(uint64_t a, uint64_t b) {
    uint64_t d;
    asm("mul.rn.f32x2 %0, %1, %2;" : "=l"(d) : "l"(a), "l"(b));
    return d;
}
__device__ __forceinline__ uint64_t add2(uint64_t a, uint64_t b) {
    uint64_t d;
    asm("add.rn.f32x2 %0, %1, %2;" : "=l"(d) : "l"(a), "l"(b));
    return d;
}
__device__ __forceinline__ uint64_t fma2(uint64_t a, uint64_t b, uint64_t c) {
    uint64_t d;
    asm("fma.rn.f32x2 %0, %1, %2, %3;" : "=l"(d) : "l"(a), "l"(b), "l"(c));
    return d;
}

// ---------------------------------------------------------------------------
// Kernel 1: prep — softmaxes, bias, bf16 B-fragment table.
// ---------------------------------------------------------------------------
__global__ void hmm_prep_kernel(const float* __restrict__ sp,
                                const float* __restrict__ trans,
                                const float* __restrict__ mu,
                                const float* __restrict__ log_var) {
    int tid = threadIdx.x, wid = tid >> 5, lane = tid & 31;

    if (wid == 0) {
        float v = sp[lane];
        float m = warpMax(v);
        float e = expf(v - m);
        float s = warpSum(e);
        g_pi[lane] = e / s;
    }
    {
        float v = trans[wid * KK + lane];
        float m = warpMax(v);
        float e = expf(v - m);
        float s = warpSum(e);
        g_expA[wid * KK + lane] = e / s;
    }
    for (int p = tid; p < 12 * 4 * 32; p += blockDim.x) {
        int s = p >> 7;
        int rem = p & 127;
        int ln = rem & 31;
        int gid = ln >> 2, tig = ln & 3;
        int n = (rem >> 5) * 8 + gid;
        float w[4];
#pragma unroll
        for (int h = 0; h < 4; ++h) {
            int row = s * 16 + tig * 2 + (h >> 1) * 8 + (h & 1);
            float v = 0.f;
            if (row < 96) {
                int d = row;
                if (d < DD) v = mu[n * DD + d] * expf(-log_var[n * DD + d]);
            } else {
                int d = row - 96;
                if (d < DD) v = -0.5f * expf(-log_var[n * DD + d]);
            }
            w[h] = v;
        }
        g_Wb[p] = make_uint2(packbf2(w[0], w[1]), packbf2(w[2], w[3]));
    }
    {
        int k = wid;
        float acc = 0.0f;
        for (int d = lane; d < DD; d += 32) {
            float lv = log_var[k * DD + d];
            float iv = expf(-lv);
            float m = mu[k * DD + d];
            acc = fmaf(m * m, iv, acc + lv);
        }
        acc = warpSum(acc);
        if (lane == 0) g_bias[k] = -0.5f * (acc + (float)DD * LOG2PI_F);
    }
}

// ---------------------------------------------------------------------------
// Kernel 2: emissions via bf16 m16n8k16 tensor cores + per-block emax sums.
// ---------------------------------------------------------------------------
__global__ void __launch_bounds__(256) hmm_emis_kernel(const float* __restrict__ X) {
    __shared__ __align__(16) uint2 ws[12 * 4 * 32];   // 12 KB
    __shared__ __align__(8) float sbias[KK];
    __shared__ float mred[8];

    int tid = threadIdx.x;
    int wid = tid >> 5, lane = tid & 31;
    int gid = lane >> 2, tig = lane & 3;

    {
        const uint4* src = (const uint4*)g_Wb;
        uint4* dst = (uint4*)ws;
#pragma unroll
        for (int i = 0; i < 3; ++i) dst[tid + 256 * i] = src[tid + 256 * i];
        if (tid < KK) sbias[tid] = g_bias[tid];
    }
    __syncthreads();

    long rowbase = (long)blockIdx.x * 128 + wid * 16;
    const float* xr0 = X + (rowbase + gid) * DD;
    const float* xr1 = xr0 + 8 * DD;

    float acc[4][4];
#pragma unroll
    for (int nt = 0; nt < 4; ++nt)
#pragma unroll
        for (int i = 0; i < 4; ++i) acc[nt][i] = 0.f;

#pragma unroll
    for (int s = 0; s < 6; ++s) {
        int c0 = s * 16 + tig * 2;
        int c1 = c0 + 8;
        float2 z = make_float2(0.f, 0.f);
        float2 f00 = (c0 < DD) ? *(const float2*)(xr0 + c0) : z;
        float2 f10 = (c0 < DD) ? *(const float2*)(xr1 + c0) : z;
        float2 f01 = (c1 < DD) ? *(const float2*)(xr0 + c1) : z;
        float2 f11 = (c1 < DD) ? *(const float2*)(xr1 + c1) : z;
        uint32_t a0 = packbf2(f00.x, f00.y), a1 = packbf2(f10.x, f10.y);
        uint32_t a2 = packbf2(f01.x, f01.y), a3 = packbf2(f11.x, f11.y);
        uint32_t q0 = packbf2(f00.x * f00.x, f00.y * f00.y);
        uint32_t q1 = packbf2(f10.x * f10.x, f10.y * f10.y);
        uint32_t q2 = packbf2(f01.x * f01.x, f01.y * f01.y);
        uint32_t q3 = packbf2(f11.x * f11.x, f11.y * f11.y);
#pragma unroll
        for (int nt = 0; nt < 4; ++nt) {
            uint2 bb = ws[(s * 4 + nt) * 32 + lane];
            mma_bf16(acc[nt][0], acc[nt][1], acc[nt][2], acc[nt][3],
                     a0, a1, a2, a3, bb.x, bb.y);
        }
#pragma unroll
        for (int nt = 0; nt < 4; ++nt) {
            uint2 bb = ws[((s + 6) * 4 + nt) * 32 + lane];
            mma_bf16(acc[nt][0], acc[nt][1], acc[nt][2], acc[nt][3],
                     q0, q1, q2, q3, bb.x, bb.y);
        }
    }

    // epilogue: +bias, row max over k, exp, store
    const float2* sb2 = (const float2*)sbias;
    float m0 = -1e30f, m1 = -1e30f;
#pragma unroll
    for (int nt = 0; nt < 4; ++nt) {
        float2 bv = sb2[nt * 4 + tig];
        acc[nt][0] += bv.x; acc[nt][1] += bv.y;
        acc[nt][2] += bv.x; acc[nt][3] += bv.y;
        m0 = fmaxf(m0, fmaxf(acc[nt][0], acc[nt][1]));
        m1 = fmaxf(m1, fmaxf(acc[nt][2], acc[nt][3]));
    }
#pragma unroll
    for (int o = 1; o <= 2; o <<= 1) {
        m0 = fmaxf(m0, __shfl_xor_sync(FULLMASK, m0, o));
        m1 = fmaxf(m1, __shfl_xor_sync(FULLMASK, m1, o));
    }
    long bt0 = rowbase + gid, bt1 = bt0 + 8;
#pragma unroll
    for (int nt = 0; nt < 4; ++nt) {
        float2 e0, e1;
        e0.x = __expf(acc[nt][0] - m0); e0.y = __expf(acc[nt][1] - m0);
        e1.x = __expf(acc[nt][2] - m1); e1.y = __expf(acc[nt][3] - m1);
        *(float2*)&g_eexp[bt0 * KK + nt * 8 + tig * 2] = e0;
        *(float2*)&g_eexp[bt1 * KK + nt * 8 + tig * 2] = e1;
    }

    // per-block sum of emax (order-independent logZ piece)
    float msum = (tig == 0) ? (m0 + m1) : 0.f;
    msum = warpSum(msum);
    if (lane == 0) mred[wid] = msum;
    __syncthreads();
    if (tid == 0) {
        float s = 0.f;
#pragma unroll
        for (int i = 0; i < 8; ++i) s += mred[i];
        g_emaxpart[blockIdx.x] = s;
    }
}

// ---------------------------------------------------------------------------
// Kernel 3: speculative chunked scan, 4 chains per warp (width-8 shuffles,
// 4 states per lane, packed f32x2 FMAs). Last-arriving block folds the final
// scalar reduction (deterministic: fixed-order array sum).
// ---------------------------------------------------------------------------
__global__ void __launch_bounds__(32) hmm_scan_kernel(float* __restrict__ out) {
    int w = blockIdx.x;            // 0 .. NBLK-1
    int lane = threadIdx.x;
    int q = lane >> 3;             // quarter -> chain within warp
    int hl = lane & 7;
    int b = w >> 3;                // 8 warps per batch
    int c = (w & 7) * 4 + q;       // chunk 0..31
    int k0 = hl * 4;               // this lane's 4 states
    const float* __restrict__ erow = g_eexp + (long)b * TT * KK;

    uint64_t A01[KK], A23[KK];     // packed columns (k0,k0+1) and (k0+2,k0+3)
#pragma unroll
    for (int j = 0; j < KK; ++j) {
        const float* a = &g_expA[j * KK + k0];
        A01[j] = pack2(a[0], a[1]);
        A23[j] = pack2(a[2], a[3]);
    }

    int tstart = c * CHUNK - WARM + 1;
    int tmin = (c == 0) ? 1 : tstart;
    int tmax = (c == CC - 1) ? (TT - 1) : (c + 1) * CHUNK;
    float u0, u1, u2, u3;
    if (c == 0) {
        u0 = g_pi[k0] * erow[k0];
        u1 = g_pi[k0 + 1] * erow[k0 + 1];
        u2 = g_pi[k0 + 2] * erow[k0 + 2];
        u3 = g_pi[k0 + 3] * erow[k0 + 3];
    } else { u0 = u1 = u2 = u3 = 1.f; }

    float logZ = 0.f;
    float4 buf[8];                 // 8-step register buffer, refilled per step
#pragma unroll
    for (int i = 0; i < 8; ++i) {
        int tc = tstart + i; tc = tc < 0 ? 0 : tc;
        buf[i] = *(const float4*)&erow[(long)tc * KK + k0];
    }

    for (int blk = 0; blk < 20; ++blk) {
        int tb = tstart + blk * 8;
#pragma unroll
        for (int i = 0; i < 8; ++i) {
            int t = tb + i;
            uint64_t acc01a, acc23a, acc01b, acc23b;
            {   // jj = 0
                float b0 = __shfl_sync(FULLMASK, u0, 0, 8);
                float b1 = __shfl_sync(FULLMASK, u1, 0, 8);
                float b2 = __shfl_sync(FULLMASK, u2, 0, 8);
                float b3 = __shfl_sync(FULLMASK, u3, 0, 8);
                uint64_t p0 = pack2(b0, b0), p1 = pack2(b1, b1);
                uint64_t p2 = pack2(b2, b2), p3 = pack2(b3, b3);
                acc01a = mul2(A01[0], p0); acc23a = mul2(A23[0], p0);
                acc01b = mul2(A01[1], p1); acc23b = mul2(A23[1], p1);
                acc01a = fma2(A01[2], p2, acc01a); acc23a = fma2(A23[2], p2, acc23a);
                acc01b = fma2(A01[3], p3, acc01b); acc23b = fma2(A23[3], p3, acc23b);
            }
#pragma unroll
            for (int jj = 1; jj < 8; ++jj) {
                float b0 = __shfl_sync(FULLMASK, u0, jj, 8);
                float b1 = __shfl_sync(FULLMASK, u1, jj, 8);
                float b2 = __shfl_sync(FULLMASK, u2, jj, 8);
                float b3 = __shfl_sync(FULLMASK, u3, jj, 8);
                uint64_t p0 = pack2(b0, b0), p1 = pack2(b1, b1);
                uint64_t p2 = pack2(b2, b2), p3 = pack2(b3, b3);
                acc01a = fma2(A01[4 * jj + 0], p0, acc01a);
                acc23a = fma2(A23[4 * jj + 0], p0, acc23a);
                acc01b = fma2(A01[4 * jj + 1], p1, acc01b);
                acc23b = fma2(A23[4 * jj + 1], p1, acc23b);
                acc01a = fma2(A01[4 * jj + 2], p2, acc01a);
                acc23a = fma2(A23[4 * jj + 2], p2, acc23a);
                acc01b = fma2(A01[4 * jj + 3], p3, acc01b);
                acc23b = fma2(A23[4 * jj + 3], p3, acc23b);
            }
            float2 r01 = unpack2(add2(acc01a, acc01b));
            float2 r23 = unpack2(add2(acc23a, acc23b));
            float4 e = buf[i];
            bool v = (t >= tmin) && (t <= tmax);
            u0 = v ? r01.x * e.x : u0;
            u1 = v ? r01.y * e.y : u1;
            u2 = v ? r23.x * e.z : u2;
            u3 = v ? r23.y * e.w : u3;
            // refill this slot for the next block (distance 8 steps)
            int tn = t + 8;
            tn = tn < 0 ? 0 : (tn > TT - 1 ? TT - 1 : tn);
            buf[i] = *(const float4*)&erow[(long)tn * KK + k0];
        }
        float S = (u0 + u1) + (u2 + u3);
#pragma unroll
        for (int o = 1; o <= 4; o <<= 1) S += __shfl_xor_sync(FULLMASK, S, o, 8);
        bool doLog = (blk >= WARM / 8);
        if (doLog || (c != 0)) {
            float rS = __frcp_rn(S);
            u0 *= rS; u1 *= rS; u2 *= rS; u3 *= rS;
        }
        if (doLog) logZ += __logf(S);
    }
    float S = (u0 + u1) + (u2 + u3);
#pragma unroll
    for (int o = 1; o <= 4; o <<= 1) S += __shfl_xor_sync(FULLMASK, S, o, 8);
    if (hl == 0) g_partial2[b * CC + c] = logZ + __logf(S);

    // ---- deterministic fused final reduction (last block to arrive) ----
    __threadfence();
    unsigned isLast = 0;
    if (lane == 0) {
        unsigned old = atomicInc(&g_ctr, NBLK - 1);   // wraps back to 0
        isLast = (old == NBLK - 1) ? 1u : 0u;
    }
    isLast = __shfl_sync(FULLMASK, isLast, 0);
    if (isLast) {
        __threadfence();
        double v = 0.0;
        const float4* p2 = (const float4*)g_partial2;
        const float4* pe = (const float4*)g_emaxpart;
        for (int i = lane; i < BB * CC / 4; i += 32) {
            float4 a = p2[i];
            v += (double)a.x + (double)a.y + (double)a.z + (double)a.w;
        }
        for (int i = lane; i < NEB / 4; i += 32) {
            float4 a = pe[i];
            v += (double)a.x + (double)a.y + (double)a.z + (double)a.w;
        }
#pragma unroll
        for (int o = 16; o > 0; o >>= 1) v += __shfl_xor_sync(FULLMASK, v, o);
        if (lane == 0) out[0] = (float)v;
    }
}

// ---------------------------------------------------------------------------
extern "C" void kernel_launch(void* const* d_in, const int* in_sizes, int n_in,
                              void* d_out, int out_size) {
    const float* X = (const float*)d_in[0];
    const float* sp = (const float*)d_in[1];
    const float* trans = (const float*)d_in[2];
    const float* mu = (const float*)d_in[3];
    const float* log_var = (const float*)d_in[4];

    hmm_prep_kernel<<<1, 1024>>>(sp, trans, mu, log_var);
    hmm_emis_kernel<<<NEB, 256>>>(X);
    hmm_scan_kernel<<<NBLK, 32>>>((float*)d_out);
}

// round 7
// speedup vs baseline: 1.4454x; 1.4454x over previous
#include <cuda_runtime.h>
#include <cuda_bf16.h>
#include <math.h>
#include <stdint.h>

#define BB 64
#define TT 4096
#define DD 90
#define KK 32
#define CC 32            // chunks per batch
#define CHUNK 128        // TT / CC
#define WARM 32          // burn-in steps (Birkhoff contraction <=0.762^32 ~ 1.6e-4)
#define NSB (BB * CC / 2)        // 1024 scan warps, 2 per block -> 512 blocks
#define NSBLK (NSB / 2)          // 512 scan blocks
#define NEB (BB * TT / 128)      // 2048 emission blocks
#define LOG2PI_F 1.8378770664093453f
#define FULLMASK 0xffffffffu

// ---- scratch (__device__ globals; no allocations allowed) ----
__device__ __align__(16) float g_eexp[BB * TT * KK];     // exp(em - emax)
__device__ __align__(16) uint2 g_Wb[12 * 4 * 32];        // bf16 B-fragment table
__device__ __align__(16) float g_bias[KK];
__device__ float g_pi[KK];
__device__ float g_expA[KK * KK];
__device__ __align__(16) float g_partial2[BB * CC];      // per-chunk log factors
__device__ __align__(16) float g_emaxpart[NEB];          // per-emis-block emax sums
__device__ unsigned g_ctr;                                // scan completion counter

__device__ __forceinline__ float warpMax(float v) {
#pragma unroll
    for (int o = 16; o > 0; o >>= 1) v = fmaxf(v, __shfl_xor_sync(FULLMASK, v, o));
    return v;
}
__device__ __forceinline__ float warpSum(float v) {
#pragma unroll
    for (int o = 16; o > 0; o >>= 1) v += __shfl_xor_sync(FULLMASK, v, o);
    return v;
}
__device__ __forceinline__ uint32_t packbf2(float lo, float hi) {
    __nv_bfloat162 h = __floats2bfloat162_rn(lo, hi);
    return *reinterpret_cast<uint32_t*>(&h);
}
__device__ __forceinline__ void mma_bf16(float& d0, float& d1, float& d2, float& d3,
                                         uint32_t a0, uint32_t a1, uint32_t a2, uint32_t a3,
                                         uint32_t b0, uint32_t b1) {
    asm volatile("mma.sync.aligned.m16n8k16.row.col.f32.bf16.bf16.f32 "
                 "{%0,%1,%2,%3},{%4,%5,%6,%7},{%8,%9},{%0,%1,%2,%3};"
                 : "+f"(d0), "+f"(d1), "+f"(d2), "+f"(d3)
                 : "r"(a0), "r"(a1), "r"(a2), "r"(a3), "r"(b0), "r"(b1));
}

// ---------------------------------------------------------------------------
// Kernel 1: prep — grid 8 x 256 to spread MUFU work across SMs.
// gw = global warp (0..63): gw<32 -> expA row gw (+ pi on gw 0);
//                           gw>=32 -> bias for k = gw-32.
// Fragment table: 1536 entries grid-strided over all 2048 threads.
// ---------------------------------------------------------------------------
__global__ void __launch_bounds__(256) hmm_prep_kernel(
        const float* __restrict__ sp, const float* __restrict__ trans,
        const float* __restrict__ mu, const float* __restrict__ log_var) {
    int tid = threadIdx.x, wid = tid >> 5, lane = tid & 31;
    int gw = blockIdx.x * 8 + wid;

    if (gw < 32) {
        float v = trans[gw * KK + lane];
        float m = warpMax(v);
        float e = expf(v - m);
        float s = warpSum(e);
        g_expA[gw * KK + lane] = e / s;
        if (gw == 0) {
            float pv = sp[lane];
            float pm = warpMax(pv);
            float pe = expf(pv - pm);
            float ps = warpSum(pe);
            g_pi[lane] = pe / ps;
        }
    } else {
        int k = gw - 32;
        float acc = 0.0f;
        for (int d = lane; d < DD; d += 32) {
            float lv = log_var[k * DD + d];
            float iv = expf(-lv);
            float m = mu[k * DD + d];
            acc = fmaf(m * m, iv, acc + lv);
        }
        acc = warpSum(acc);
        if (lane == 0) g_bias[k] = -0.5f * (acc + (float)DD * LOG2PI_F);
    }

    int p = blockIdx.x * 256 + tid;
    if (p < 12 * 4 * 32) {
        int s = p >> 7;
        int rem = p & 127;
        int ln = rem & 31;
        int gid = ln >> 2, tig = ln & 3;
        int n = (rem >> 5) * 8 + gid;
        float w[4];
#pragma unroll
        for (int h = 0; h < 4; ++h) {
            int row = s * 16 + tig * 2 + (h >> 1) * 8 + (h & 1);
            float v = 0.f;
            if (row < 96) {
                int d = row;
                if (d < DD) v = mu[n * DD + d] * expf(-log_var[n * DD + d]);
            } else {
                int d = row - 96;
                if (d < DD) v = -0.5f * expf(-log_var[n * DD + d]);
            }
            w[h] = v;
        }
        g_Wb[p] = make_uint2(packbf2(w[0], w[1]), packbf2(w[2], w[3]));
    }
}

// ---------------------------------------------------------------------------
// Kernel 2: emissions via bf16 m16n8k16 tensor cores + per-block emax sums.
// ---------------------------------------------------------------------------
__global__ void __launch_bounds__(256) hmm_emis_kernel(const float* __restrict__ X) {
    __shared__ __align__(16) uint2 ws[12 * 4 * 32];   // 12 KB
    __shared__ __align__(8) float sbias[KK];
    __shared__ float mred[8];

    int tid = threadIdx.x;
    int wid = tid >> 5, lane = tid & 31;
    int gid = lane >> 2, tig = lane & 3;

    {
        const uint4* src = (const uint4*)g_Wb;
        uint4* dst = (uint4*)ws;
#pragma unroll
        for (int i = 0; i < 3; ++i) dst[tid + 256 * i] = src[tid + 256 * i];
        if (tid < KK) sbias[tid] = g_bias[tid];
    }
    __syncthreads();

    long rowbase = (long)blockIdx.x * 128 + wid * 16;
    const float* xr0 = X + (rowbase + gid) * DD;
    const float* xr1 = xr0 + 8 * DD;

    float acc[4][4];
#pragma unroll
    for (int nt = 0; nt < 4; ++nt)
#pragma unroll
        for (int i = 0; i < 4; ++i) acc[nt][i] = 0.f;

#pragma unroll
    for (int s = 0; s < 6; ++s) {
        int c0 = s * 16 + tig * 2;
        int c1 = c0 + 8;
        float2 z = make_float2(0.f, 0.f);
        float2 f00 = (c0 < DD) ? *(const float2*)(xr0 + c0) : z;
        float2 f10 = (c0 < DD) ? *(const float2*)(xr1 + c0) : z;
        float2 f01 = (c1 < DD) ? *(const float2*)(xr0 + c1) : z;
        float2 f11 = (c1 < DD) ? *(const float2*)(xr1 + c1) : z;
        uint32_t a0 = packbf2(f00.x, f00.y), a1 = packbf2(f10.x, f10.y);
        uint32_t a2 = packbf2(f01.x, f01.y), a3 = packbf2(f11.x, f11.y);
        uint32_t q0 = packbf2(f00.x * f00.x, f00.y * f00.y);
        uint32_t q1 = packbf2(f10.x * f10.x, f10.y * f10.y);
        uint32_t q2 = packbf2(f01.x * f01.x, f01.y * f01.y);
        uint32_t q3 = packbf2(f11.x * f11.x, f11.y * f11.y);
#pragma unroll
        for (int nt = 0; nt < 4; ++nt) {
            uint2 bb = ws[(s * 4 + nt) * 32 + lane];
            mma_bf16(acc[nt][0], acc[nt][1], acc[nt][2], acc[nt][3],
                     a0, a1, a2, a3, bb.x, bb.y);
        }
#pragma unroll
        for (int nt = 0; nt < 4; ++nt) {
            uint2 bb = ws[((s + 6) * 4 + nt) * 32 + lane];
            mma_bf16(acc[nt][0], acc[nt][1], acc[nt][2], acc[nt][3],
                     q0, q1, q2, q3, bb.x, bb.y);
        }
    }

    // epilogue: +bias, row max over k, exp, store
    const float2* sb2 = (const float2*)sbias;
    float m0 = -1e30f, m1 = -1e30f;
#pragma unroll
    for (int nt = 0; nt < 4; ++nt) {
        float2 bv = sb2[nt * 4 + tig];
        acc[nt][0] += bv.x; acc[nt][1] += bv.y;
        acc[nt][2] += bv.x; acc[nt][3] += bv.y;
        m0 = fmaxf(m0, fmaxf(acc[nt][0], acc[nt][1]));
        m1 = fmaxf(m1, fmaxf(acc[nt][2], acc[nt][3]));
    }
#pragma unroll
    for (int o = 1; o <= 2; o <<= 1) {
        m0 = fmaxf(m0, __shfl_xor_sync(FULLMASK, m0, o));
        m1 = fmaxf(m1, __shfl_xor_sync(FULLMASK, m1, o));
    }
    long bt0 = rowbase + gid, bt1 = bt0 + 8;
#pragma unroll
    for (int nt = 0; nt < 4; ++nt) {
        float2 e0, e1;
        e0.x = __expf(acc[nt][0] - m0); e0.y = __expf(acc[nt][1] - m0);
        e1.x = __expf(acc[nt][2] - m1); e1.y = __expf(acc[nt][3] - m1);
        *(float2*)&g_eexp[bt0 * KK + nt * 8 + tig * 2] = e0;
        *(float2*)&g_eexp[bt1 * KK + nt * 8 + tig * 2] = e1;
    }

    // per-block sum of emax (order-independent logZ piece)
    float msum = (tig == 0) ? (m0 + m1) : 0.f;
    msum = warpSum(msum);
    if (lane == 0) mred[wid] = msum;
    __syncthreads();
    if (tid == 0) {
        float s = 0.f;
#pragma unroll
        for (int i = 0; i < 8; ++i) s += mred[i];
        g_emaxpart[blockIdx.x] = s;
    }
}

// ---------------------------------------------------------------------------
// Kernel 3: speculative chunked scan, 2 chains per warp (round-5 layout:
// lanes 0-15 / 16-31 = chains; 2 states per lane; width-16 shuffles).
// Last-arriving block performs the deterministic final reduction.
// ---------------------------------------------------------------------------
__global__ void __launch_bounds__(64) hmm_scan_kernel(float* __restrict__ out) {
    int w = blockIdx.x * 2 + (threadIdx.x >> 5);   // 0 .. BB*CC/2-1
    int lane = threadIdx.x & 31;
    int half = lane >> 4;
    int hl = lane & 15;
    int b = w >> 4;                // 16 chain-pairs per batch
    int cp = w & 15;
    int c = cp * 2 + half;
    int k0 = hl * 2;
    const float* __restrict__ erow = g_eexp + (long)b * TT * KK;

    float A0[KK], A1[KK];
#pragma unroll
    for (int j = 0; j < KK; ++j) {
        A0[j] = g_expA[j * KK + k0];
        A1[j] = g_expA[j * KK + k0 + 1];
    }

    int tstart = c * CHUNK - WARM + 1;                 // c=0 -> -31
    int tmin = (c == 0) ? 1 : tstart;
    int tmax = (c == CC - 1) ? (TT - 1) : (c + 1) * CHUNK;
    float u0, u1;
    if (c == 0) { u0 = g_pi[k0] * erow[k0]; u1 = g_pi[k0 + 1] * erow[k0 + 1]; }
    else        { u0 = 1.f; u1 = 1.f; }

    float logZ = 0.f;
    float2 bufA[8], bufB[8];
#pragma unroll
    for (int i = 0; i < 8; ++i) {
        int tc = tstart + i; tc = tc < 0 ? 0 : tc;
        bufA[i] = *(const float2*)&erow[(long)tc * KK + k0];
    }

    for (int blk = 0; blk < 20; ++blk) {
        int tb = tstart + blk * 8;
#pragma unroll
        for (int i = 0; i < 8; ++i) {
            int tc = tb + 8 + i;
            tc = tc < 0 ? 0 : (tc > TT - 1 ? TT - 1 : tc);
            bufB[i] = *(const float2*)&erow[(long)tc * KK + k0];
        }
#pragma unroll
        for (int i = 0; i < 8; ++i) {
            int t = tb + i;
            float s0a = 0.f, s0b = 0.f, s1a = 0.f, s1b = 0.f;
#pragma unroll
            for (int jj = 0; jj < 16; ++jj) {
                float bu0 = __shfl_sync(FULLMASK, u0, jj, 16);
                float bu1 = __shfl_sync(FULLMASK, u1, jj, 16);
                s0a = fmaf(bu0, A0[2 * jj], s0a);
                s1a = fmaf(bu0, A1[2 * jj], s1a);
                s0b = fmaf(bu1, A0[2 * jj + 1], s0b);
                s1b = fmaf(bu1, A1[2 * jj + 1], s1b);
            }
            bool v = (t >= tmin) && (t <= tmax);
            float n0 = bufA[i].x * (s0a + s0b);
            float n1 = bufA[i].y * (s1a + s1b);
            u0 = v ? n0 : u0;
            u1 = v ? n1 : u1;
        }
        float S = u0 + u1;
#pragma unroll
        for (int o = 1; o <= 8; o <<= 1) S += __shfl_xor_sync(FULLMASK, S, o);
        bool doLog = (blk >= WARM / 8);
        if (doLog || (c != 0)) {
            float rS = __frcp_rn(S);
            u0 *= rS; u1 *= rS;
        }
        if (doLog) logZ += __logf(S);
#pragma unroll
        for (int i = 0; i < 8; ++i) bufA[i] = bufB[i];
    }
    float S = u0 + u1;
#pragma unroll
    for (int o = 1; o <= 8; o <<= 1) S += __shfl_xor_sync(FULLMASK, S, o);
    if (hl == 0) g_partial2[b * CC + c] = logZ + __logf(S);

    // ---- deterministic fused final reduction (last block to arrive) ----
    __threadfence();
    __syncthreads();                       // both warps' stores done
    unsigned isLast = 0;
    if (threadIdx.x == 0) {
        unsigned old = atomicInc(&g_ctr, NSBLK - 1);   // wraps back to 0
        isLast = (old == NSBLK - 1) ? 1u : 0u;
    }
    isLast = __shfl_sync(FULLMASK, isLast, 0);
    if ((threadIdx.x >> 5) == 0 && isLast) {
        __threadfence();
        double v = 0.0;
        const float4* p2 = (const float4*)g_partial2;
        const float4* pe = (const float4*)g_emaxpart;
        for (int i = lane; i < BB * CC / 4; i += 32) {
            float4 a = p2[i];
            v += (double)a.x + (double)a.y + (double)a.z + (double)a.w;
        }
        for (int i = lane; i < NEB / 4; i += 32) {
            float4 a = pe[i];
            v += (double)a.x + (double)a.y + (double)a.z + (double)a.w;
        }
#pragma unroll
        for (int o = 16; o > 0; o >>= 1) v += __shfl_xor_sync(FULLMASK, v, o);
        if (lane == 0) out[0] = (float)v;
    }
}

// ---------------------------------------------------------------------------
extern "C" void kernel_launch(void* const* d_in, const int* in_sizes, int n_in,
                              void* d_out, int out_size) {
    const float* X = (const float*)d_in[0];
    const float* sp = (const float*)d_in[1];
    const float* trans = (const float*)d_in[2];
    const float* mu = (const float*)d_in[3];
    const float* log_var = (const float*)d_in[4];

    hmm_prep_kernel<<<8, 256>>>(sp, trans, mu, log_var);
    hmm_emis_kernel<<<NEB, 256>>>(X);
    hmm_scan_kernel<<<NSBLK, 64>>>((float*)d_out);
}

// round 8
// speedup vs baseline: 1.7639x; 1.2204x over previous
#include <cuda_runtime.h>
#include <cuda_bf16.h>
#include <math.h>
#include <stdint.h>

#define BB 64
#define TT 4096
#define DD 90
#define KK 32
#define CC 32            // chunks per batch
#define CHUNK 128        // TT / CC
#define WARM 16          // burn-in steps (contraction 0.46^16 ~ 4e-6 per chunk)
#define NSBLK (BB * CC / 4)      // 512 scan blocks (2 warps x 2 chains)
#define NEB (BB * TT / 128)      // 2048 emission blocks
#define LOG2PI_F 1.8378770664093453f
#define FULLMASK 0xffffffffu

// ---- scratch (__device__ globals; no allocations allowed) ----
__device__ __align__(16) float g_eexp[BB * TT * KK];     // exp(em - emax)
__device__ __align__(16) uint2 g_Wb[12 * 4 * 32];        // bf16 B-fragment table
__device__ __align__(16) float g_bias[KK];
__device__ float g_pi[KK];
__device__ float g_expA[KK * KK];
__device__ __align__(16) float g_partial2[BB * CC];      // per-chunk log factors
__device__ __align__(16) float g_emaxpart[NEB];          // per-emis-block emax sums

__device__ __forceinline__ float warpMax(float v) {
#pragma unroll
    for (int o = 16; o > 0; o >>= 1) v = fmaxf(v, __shfl_xor_sync(FULLMASK, v, o));
    return v;
}
__device__ __forceinline__ float warpSum(float v) {
#pragma unroll
    for (int o = 16; o > 0; o >>= 1) v += __shfl_xor_sync(FULLMASK, v, o);
    return v;
}
__device__ __forceinline__ uint32_t packbf2(float lo, float hi) {
    __nv_bfloat162 h = __floats2bfloat162_rn(lo, hi);
    return *reinterpret_cast<uint32_t*>(&h);
}
__device__ __forceinline__ void mma_bf16(float& d0, float& d1, float& d2, float& d3,
                                         uint32_t a0, uint32_t a1, uint32_t a2, uint32_t a3,
                                         uint32_t b0, uint32_t b1) {
    asm volatile("mma.sync.aligned.m16n8k16.row.col.f32.bf16.bf16.f32 "
                 "{%0,%1,%2,%3},{%4,%5,%6,%7},{%8,%9},{%0,%1,%2,%3};"
                 : "+f"(d0), "+f"(d1), "+f"(d2), "+f"(d3)
                 : "r"(a0), "r"(a1), "r"(a2), "r"(a3), "r"(b0), "r"(b1));
}

// ---------------------------------------------------------------------------
// Kernel 1: prep — grid 8 x 256 (spread MUFU across SMs).
// ---------------------------------------------------------------------------
__global__ void __launch_bounds__(256) hmm_prep_kernel(
        const float* __restrict__ sp, const float* __restrict__ trans,
        const float* __restrict__ mu, const float* __restrict__ log_var) {
    int tid = threadIdx.x, wid = tid >> 5, lane = tid & 31;
    int gw = blockIdx.x * 8 + wid;

    if (gw < 32) {
        float v = trans[gw * KK + lane];
        float m = warpMax(v);
        float e = expf(v - m);
        float s = warpSum(e);
        g_expA[gw * KK + lane] = e / s;
        if (gw == 0) {
            float pv = sp[lane];
            float pm = warpMax(pv);
            float pe = expf(pv - pm);
            float ps = warpSum(pe);
            g_pi[lane] = pe / ps;
        }
    } else {
        int k = gw - 32;
        float acc = 0.0f;
        for (int d = lane; d < DD; d += 32) {
            float lv = log_var[k * DD + d];
            float iv = expf(-lv);
            float m = mu[k * DD + d];
            acc = fmaf(m * m, iv, acc + lv);
        }
        acc = warpSum(acc);
        if (lane == 0) g_bias[k] = -0.5f * (acc + (float)DD * LOG2PI_F);
    }

    int p = blockIdx.x * 256 + tid;
    if (p < 12 * 4 * 32) {
        int s = p >> 7;
        int rem = p & 127;
        int ln = rem & 31;
        int gid = ln >> 2, tig = ln & 3;
        int n = (rem >> 5) * 8 + gid;
        float w[4];
#pragma unroll
        for (int h = 0; h < 4; ++h) {
            int row = s * 16 + tig * 2 + (h >> 1) * 8 + (h & 1);
            float v = 0.f;
            if (row < 96) {
                int d = row;
                if (d < DD) v = mu[n * DD + d] * expf(-log_var[n * DD + d]);
            } else {
                int d = row - 96;
                if (d < DD) v = -0.5f * expf(-log_var[n * DD + d]);
            }
            w[h] = v;
        }
        g_Wb[p] = make_uint2(packbf2(w[0], w[1]), packbf2(w[2], w[3]));
    }
}

// ---------------------------------------------------------------------------
// Kernel 2: emissions via bf16 m16n8k16 tensor cores.
// X staged through shared memory (coalesced float4 in, LDS.64 out).
// block = 256 thr, tile = 128 rows x 32 states; per-block emax partial sums.
// ---------------------------------------------------------------------------
__global__ void __launch_bounds__(256) hmm_emis_kernel(const float* __restrict__ X) {
    __shared__ __align__(16) float xs[128 * DD];       // 46.08 KB
    __shared__ __align__(16) uint2 ws[12 * 4 * 32];    // 12 KB
    __shared__ __align__(8) float sbias[KK];
    __shared__ float mred[8];

    int tid = threadIdx.x;
    int wid = tid >> 5, lane = tid & 31;
    int gid = lane >> 2, tig = lane & 3;

    {   // stage weights + X tile (128*90 floats = 2880 float4, contiguous)
        const uint4* src = (const uint4*)g_Wb;
        uint4* dst = (uint4*)ws;
#pragma unroll
        for (int i = 0; i < 3; ++i) dst[tid + 256 * i] = src[tid + 256 * i];
        if (tid < KK) sbias[tid] = g_bias[tid];
        const float4* X4 = (const float4*)(X + (long)blockIdx.x * 128 * DD);
        float4* xs4 = (float4*)xs;
#pragma unroll
        for (int i = 0; i < 11; ++i) xs4[tid + 256 * i] = X4[tid + 256 * i];
        if (tid < 2880 - 2816) xs4[tid + 2816] = X4[tid + 2816];
    }
    __syncthreads();

    const float* xr0 = xs + (wid * 16 + gid) * DD;
    const float* xr1 = xr0 + 8 * DD;

    float acc[4][4];
#pragma unroll
    for (int nt = 0; nt < 4; ++nt)
#pragma unroll
        for (int i = 0; i < 4; ++i) acc[nt][i] = 0.f;

#pragma unroll
    for (int s = 0; s < 6; ++s) {
        int c0 = s * 16 + tig * 2;
        int c1 = c0 + 8;
        float2 z = make_float2(0.f, 0.f);
        float2 f00 = (c0 < DD) ? *(const float2*)(xr0 + c0) : z;
        float2 f10 = (c0 < DD) ? *(const float2*)(xr1 + c0) : z;
        float2 f01 = (c1 < DD) ? *(const float2*)(xr0 + c1) : z;
        float2 f11 = (c1 < DD) ? *(const float2*)(xr1 + c1) : z;
        uint32_t a0 = packbf2(f00.x, f00.y), a1 = packbf2(f10.x, f10.y);
        uint32_t a2 = packbf2(f01.x, f01.y), a3 = packbf2(f11.x, f11.y);
        uint32_t q0 = packbf2(f00.x * f00.x, f00.y * f00.y);
        uint32_t q1 = packbf2(f10.x * f10.x, f10.y * f10.y);
        uint32_t q2 = packbf2(f01.x * f01.x, f01.y * f01.y);
        uint32_t q3 = packbf2(f11.x * f11.x, f11.y * f11.y);
#pragma unroll
        for (int nt = 0; nt < 4; ++nt) {
            uint2 bb = ws[(s * 4 + nt) * 32 + lane];
            mma_bf16(acc[nt][0], acc[nt][1], acc[nt][2], acc[nt][3],
                     a0, a1, a2, a3, bb.x, bb.y);
        }
#pragma unroll
        for (int nt = 0; nt < 4; ++nt) {
            uint2 bb = ws[((s + 6) * 4 + nt) * 32 + lane];
            mma_bf16(acc[nt][0], acc[nt][1], acc[nt][2], acc[nt][3],
                     q0, q1, q2, q3, bb.x, bb.y);
        }
    }

    // epilogue: +bias, row max over k, exp, store
    const float2* sb2 = (const float2*)sbias;
    float m0 = -1e30f, m1 = -1e30f;
#pragma unroll
    for (int nt = 0; nt < 4; ++nt) {
        float2 bv = sb2[nt * 4 + tig];
        acc[nt][0] += bv.x; acc[nt][1] += bv.y;
        acc[nt][2] += bv.x; acc[nt][3] += bv.y;
        m0 = fmaxf(m0, fmaxf(acc[nt][0], acc[nt][1]));
        m1 = fmaxf(m1, fmaxf(acc[nt][2], acc[nt][3]));
    }
#pragma unroll
    for (int o = 1; o <= 2; o <<= 1) {
        m0 = fmaxf(m0, __shfl_xor_sync(FULLMASK, m0, o));
        m1 = fmaxf(m1, __shfl_xor_sync(FULLMASK, m1, o));
    }
    long bt0 = (long)blockIdx.x * 128 + wid * 16 + gid;
    long bt1 = bt0 + 8;
#pragma unroll
    for (int nt = 0; nt < 4; ++nt) {
        float2 e0, e1;
        e0.x = __expf(acc[nt][0] - m0); e0.y = __expf(acc[nt][1] - m0);
        e1.x = __expf(acc[nt][2] - m1); e1.y = __expf(acc[nt][3] - m1);
        *(float2*)&g_eexp[bt0 * KK + nt * 8 + tig * 2] = e0;
        *(float2*)&g_eexp[bt1 * KK + nt * 8 + tig * 2] = e1;
    }

    float msum = (tig == 0) ? (m0 + m1) : 0.f;
    msum = warpSum(msum);
    if (lane == 0) mred[wid] = msum;
    __syncthreads();
    if (tid == 0) {
        float s = 0.f;
#pragma unroll
        for (int i = 0; i < 8; ++i) s += mred[i];
        g_emaxpart[blockIdx.x] = s;
    }
}

// ---------------------------------------------------------------------------
// Kernel 3: speculative chunked scan, 2 chains per warp (R5 layout).
// ---------------------------------------------------------------------------
__global__ void __launch_bounds__(64) hmm_scan_kernel() {
    int w = blockIdx.x * 2 + (threadIdx.x >> 5);   // 0 .. BB*CC/2-1
    int lane = threadIdx.x & 31;
    int half = lane >> 4;
    int hl = lane & 15;
    int b = w >> 4;                // 16 chain-pairs per batch
    int cp = w & 15;
    int c = cp * 2 + half;
    int k0 = hl * 2;
    const float* __restrict__ erow = g_eexp + (long)b * TT * KK;

    float A0[KK], A1[KK];
#pragma unroll
    for (int j = 0; j < KK; ++j) {
        A0[j] = g_expA[j * KK + k0];
        A1[j] = g_expA[j * KK + k0 + 1];
    }

    int tstart = c * CHUNK - WARM + 1;                 // c=0 -> -15
    int tmin = (c == 0) ? 1 : tstart;
    int tmax = (c == CC - 1) ? (TT - 1) : (c + 1) * CHUNK;
    float u0, u1;
    if (c == 0) { u0 = g_pi[k0] * erow[k0]; u1 = g_pi[k0 + 1] * erow[k0 + 1]; }
    else        { u0 = 1.f; u1 = 1.f; }

    float logZ = 0.f;
    float2 bufA[8], bufB[8];
#pragma unroll
    for (int i = 0; i < 8; ++i) {
        int tc = tstart + i; tc = tc < 0 ? 0 : tc;
        bufA[i] = *(const float2*)&erow[(long)tc * KK + k0];
    }

    for (int blk = 0; blk < (WARM + CHUNK) / 8; ++blk) {   // 18 blocks
        int tb = tstart + blk * 8;
#pragma unroll
        for (int i = 0; i < 8; ++i) {
            int tc = tb + 8 + i;
            tc = tc < 0 ? 0 : (tc > TT - 1 ? TT - 1 : tc);
            bufB[i] = *(const float2*)&erow[(long)tc * KK + k0];
        }
#pragma unroll
        for (int i = 0; i < 8; ++i) {
            int t = tb + i;
            float s0a = 0.f, s0b = 0.f, s1a = 0.f, s1b = 0.f;
#pragma unroll
            for (int jj = 0; jj < 16; ++jj) {
                float bu0 = __shfl_sync(FULLMASK, u0, jj, 16);
                float bu1 = __shfl_sync(FULLMASK, u1, jj, 16);
                s0a = fmaf(bu0, A0[2 * jj], s0a);
                s1a = fmaf(bu0, A1[2 * jj], s1a);
                s0b = fmaf(bu1, A0[2 * jj + 1], s0b);
                s1b = fmaf(bu1, A1[2 * jj + 1], s1b);
            }
            bool v = (t >= tmin) && (t <= tmax);
            float n0 = bufA[i].x * (s0a + s0b);
            float n1 = bufA[i].y * (s1a + s1b);
            u0 = v ? n0 : u0;
            u1 = v ? n1 : u1;
        }
        float S = u0 + u1;
#pragma unroll
        for (int o = 1; o <= 8; o <<= 1) S += __shfl_xor_sync(FULLMASK, S, o);
        bool doLog = (blk >= WARM / 8);
        if (doLog || (c != 0)) {
            float rS = __frcp_rn(S);
            u0 *= rS; u1 *= rS;
        }
        if (doLog) logZ += __logf(S);
#pragma unroll
        for (int i = 0; i < 8; ++i) bufA[i] = bufB[i];
    }
    float S = u0 + u1;
#pragma unroll
    for (int o = 1; o <= 8; o <<= 1) S += __shfl_xor_sync(FULLMASK, S, o);
    if (hl == 0) g_partial2[b * CC + c] = logZ + __logf(S);
}

// ---------------------------------------------------------------------------
// Kernel 4: final scalar (deterministic fixed-order double reduction)
// ---------------------------------------------------------------------------
__global__ void __launch_bounds__(256) hmm_final_kernel(float* __restrict__ out) {
    __shared__ double red[8];
    int tid = threadIdx.x;
    double v = 0.0;
    const float4* p2 = (const float4*)g_partial2;
    const float4* pe = (const float4*)g_emaxpart;
#pragma unroll
    for (int i = tid; i < BB * CC / 4; i += 256) {
        float4 a = p2[i];
        v += (double)a.x + (double)a.y + (double)a.z + (double)a.w;
    }
#pragma unroll
    for (int i = tid; i < NEB / 4; i += 256) {
        float4 a = pe[i];
        v += (double)a.x + (double)a.y + (double)a.z + (double)a.w;
    }
#pragma unroll
    for (int o = 16; o > 0; o >>= 1) v += __shfl_xor_sync(FULLMASK, v, o);
    if ((tid & 31) == 0) red[tid >> 5] = v;
    __syncthreads();
    if (tid < 8) {
        double wv = red[tid];
#pragma unroll
        for (int o = 4; o > 0; o >>= 1) wv += __shfl_xor_sync(0xff, wv, o);
        if (tid == 0) out[0] = (float)wv;
    }
}

// ---------------------------------------------------------------------------
extern "C" void kernel_launch(void* const* d_in, const int* in_sizes, int n_in,
                              void* d_out, int out_size) {
    const float* X = (const float*)d_in[0];
    const float* sp = (const float*)d_in[1];
    const float* trans = (const float*)d_in[2];
    const float* mu = (const float*)d_in[3];
    const float* log_var = (const float*)d_in[4];

    hmm_prep_kernel<<<8, 256>>>(sp, trans, mu, log_var);
    hmm_emis_kernel<<<NEB, 256>>>(X);
    hmm_scan_kernel<<<NSBLK, 64>>>();
    hmm_final_kernel<<<1, 256>>>((float*)d_out);
}

// round 9
// speedup vs baseline: 1.8090x; 1.0255x over previous
#include <cuda_runtime.h>
#include <cuda_bf16.h>
#include <math.h>
#include <stdint.h>

#define BB 64
#define TT 4096
#define DD 90
#define KK 32
#define CC 64            // chunks per batch
#define CHUNK 64         // TT / CC
#define WARM 16          // burn-in steps (contraction 0.46^16 ~ 4e-6 per chunk)
#define NSTEP (WARM + CHUNK)     // 80
#define PADF 16
#define ERows (PADF + TT + 8)    // 4120 padded rows per batch (pads stay zero)
#define NEB (BB * TT / 128)      // 2048 emission blocks
#define LOG2PI_F 1.8378770664093453f
#define FULLMASK 0xffffffffu

// ---- scratch (__device__ globals; no allocations allowed) ----
__device__ __align__(16) float g_eexp[BB * ERows * KK];  // exp(em-emax), padded
__device__ __align__(16) uint2 g_Wb[12 * 4 * 32];        // bf16 B-fragment table
__device__ __align__(16) float g_bias[KK];
__device__ float g_pi[KK];
__device__ float g_expA[KK * KK];
__device__ __align__(16) float g_partial2[BB * CC];      // per-chunk log factors
__device__ __align__(16) float g_emaxpart[NEB];          // per-emis-block emax sums

__device__ __forceinline__ float warpMax(float v) {
#pragma unroll
    for (int o = 16; o > 0; o >>= 1) v = fmaxf(v, __shfl_xor_sync(FULLMASK, v, o));
    return v;
}
__device__ __forceinline__ float warpSum(float v) {
#pragma unroll
    for (int o = 16; o > 0; o >>= 1) v += __shfl_xor_sync(FULLMASK, v, o);
    return v;
}
__device__ __forceinline__ uint32_t packbf2(float lo, float hi) {
    __nv_bfloat162 h = __floats2bfloat162_rn(lo, hi);
    return *reinterpret_cast<uint32_t*>(&h);
}
__device__ __forceinline__ void mma_bf16(float& d0, float& d1, float& d2, float& d3,
                                         uint32_t a0, uint32_t a1, uint32_t a2, uint32_t a3,
                                         uint32_t b0, uint32_t b1) {
    asm volatile("mma.sync.aligned.m16n8k16.row.col.f32.bf16.bf16.f32 "
                 "{%0,%1,%2,%3},{%4,%5,%6,%7},{%8,%9},{%0,%1,%2,%3};"
                 : "+f"(d0), "+f"(d1), "+f"(d2), "+f"(d3)
                 : "r"(a0), "r"(a1), "r"(a2), "r"(a3), "r"(b0), "r"(b1));
}
// MMA with zero C (independent accumulation streams)
__device__ __forceinline__ void mma_bf16_z(float* d,
                                           uint32_t a0, uint32_t a1, uint32_t a2, uint32_t a3,
                                           uint32_t b0, uint32_t b1) {
    asm volatile("mma.sync.aligned.m16n8k16.row.col.f32.bf16.bf16.f32 "
                 "{%0,%1,%2,%3},{%4,%5,%6,%7},{%8,%9},{%10,%10,%10,%10};"
                 : "=f"(d[0]), "=f"(d[1]), "=f"(d[2]), "=f"(d[3])
                 : "r"(a0), "r"(a1), "r"(a2), "r"(a3), "r"(b0), "r"(b1), "f"(0.0f));
}

// ---------------------------------------------------------------------------
// Kernel 1: prep — grid 8 x 256 (spread MUFU across SMs).
// ---------------------------------------------------------------------------
__global__ void __launch_bounds__(256) hmm_prep_kernel(
        const float* __restrict__ sp, const float* __restrict__ trans,
        const float* __restrict__ mu, const float* __restrict__ log_var) {
    int tid = threadIdx.x, wid = tid >> 5, lane = tid & 31;
    int gw = blockIdx.x * 8 + wid;

    if (gw < 32) {
        float v = trans[gw * KK + lane];
        float m = warpMax(v);
        float e = expf(v - m);
        float s = warpSum(e);
        g_expA[gw * KK + lane] = e / s;
        if (gw == 0) {
            float pv = sp[lane];
            float pm = warpMax(pv);
            float pe = expf(pv - pm);
            float ps = warpSum(pe);
            g_pi[lane] = pe / ps;
        }
    } else {
        int k = gw - 32;
        float acc = 0.0f;
        for (int d = lane; d < DD; d += 32) {
            float lv = log_var[k * DD + d];
            float iv = expf(-lv);
            float m = mu[k * DD + d];
            acc = fmaf(m * m, iv, acc + lv);
        }
        acc = warpSum(acc);
        if (lane == 0) g_bias[k] = -0.5f * (acc + (float)DD * LOG2PI_F);
    }

    int p = blockIdx.x * 256 + tid;
    if (p < 12 * 4 * 32) {
        int s = p >> 7;
        int rem = p & 127;
        int ln = rem & 31;
        int gid = ln >> 2, tig = ln & 3;
        int n = (rem >> 5) * 8 + gid;
        float w[4];
#pragma unroll
        for (int h = 0; h < 4; ++h) {
            int row = s * 16 + tig * 2 + (h >> 1) * 8 + (h & 1);
            float v = 0.f;
            if (row < 96) {
                int d = row;
                if (d < DD) v = mu[n * DD + d] * expf(-log_var[n * DD + d]);
            } else {
                int d = row - 96;
                if (d < DD) v = -0.5f * expf(-log_var[n * DD + d]);
            }
            w[h] = v;
        }
        g_Wb[p] = make_uint2(packbf2(w[0], w[1]), packbf2(w[2], w[3]));
    }
}

// ---------------------------------------------------------------------------
// Kernel 2: emissions via bf16 m16n8k16 tensor cores (writes padded g_eexp).
// ---------------------------------------------------------------------------
__global__ void __launch_bounds__(256) hmm_emis_kernel(const float* __restrict__ X) {
    __shared__ __align__(16) float xs[128 * DD];       // 46.08 KB
    __shared__ __align__(16) uint2 ws[12 * 4 * 32];    // 12 KB
    __shared__ __align__(8) float sbias[KK];
    __shared__ float mred[8];

    int tid = threadIdx.x;
    int wid = tid >> 5, lane = tid & 31;
    int gid = lane >> 2, tig = lane & 3;

    {
        const uint4* src = (const uint4*)g_Wb;
        uint4* dst = (uint4*)ws;
#pragma unroll
        for (int i = 0; i < 3; ++i) dst[tid + 256 * i] = src[tid + 256 * i];
        if (tid < KK) sbias[tid] = g_bias[tid];
        const float4* X4 = (const float4*)(X + (long)blockIdx.x * 128 * DD);
        float4* xs4 = (float4*)xs;
#pragma unroll
        for (int i = 0; i < 11; ++i) xs4[tid + 256 * i] = X4[tid + 256 * i];
        if (tid < 2880 - 2816) xs4[tid + 2816] = X4[tid + 2816];
    }
    __syncthreads();

    const float* xr0 = xs + (wid * 16 + gid) * DD;
    const float* xr1 = xr0 + 8 * DD;

    float acc[4][4];
#pragma unroll
    for (int nt = 0; nt < 4; ++nt)
#pragma unroll
        for (int i = 0; i < 4; ++i) acc[nt][i] = 0.f;

#pragma unroll
    for (int s = 0; s < 6; ++s) {
        int c0 = s * 16 + tig * 2;
        int c1 = c0 + 8;
        float2 z = make_float2(0.f, 0.f);
        float2 f00 = (c0 < DD) ? *(const float2*)(xr0 + c0) : z;
        float2 f10 = (c0 < DD) ? *(const float2*)(xr1 + c0) : z;
        float2 f01 = (c1 < DD) ? *(const float2*)(xr0 + c1) : z;
        float2 f11 = (c1 < DD) ? *(const float2*)(xr1 + c1) : z;
        uint32_t a0 = packbf2(f00.x, f00.y), a1 = packbf2(f10.x, f10.y);
        uint32_t a2 = packbf2(f01.x, f01.y), a3 = packbf2(f11.x, f11.y);
        uint32_t q0 = packbf2(f00.x * f00.x, f00.y * f00.y);
        uint32_t q1 = packbf2(f10.x * f10.x, f10.y * f10.y);
        uint32_t q2 = packbf2(f01.x * f01.x, f01.y * f01.y);
        uint32_t q3 = packbf2(f11.x * f11.x, f11.y * f11.y);
#pragma unroll
        for (int nt = 0; nt < 4; ++nt) {
            uint2 bb = ws[(s * 4 + nt) * 32 + lane];
            mma_bf16(acc[nt][0], acc[nt][1], acc[nt][2], acc[nt][3],
                     a0, a1, a2, a3, bb.x, bb.y);
        }
#pragma unroll
        for (int nt = 0; nt < 4; ++nt) {
            uint2 bb = ws[((s + 6) * 4 + nt) * 32 + lane];
            mma_bf16(acc[nt][0], acc[nt][1], acc[nt][2], acc[nt][3],
                     q0, q1, q2, q3, bb.x, bb.y);
        }
    }

    const float2* sb2 = (const float2*)sbias;
    float m0 = -1e30f, m1 = -1e30f;
#pragma unroll
    for (int nt = 0; nt < 4; ++nt) {
        float2 bv = sb2[nt * 4 + tig];
        acc[nt][0] += bv.x; acc[nt][1] += bv.y;
        acc[nt][2] += bv.x; acc[nt][3] += bv.y;
        m0 = fmaxf(m0, fmaxf(acc[nt][0], acc[nt][1]));
        m1 = fmaxf(m1, fmaxf(acc[nt][2], acc[nt][3]));
    }
#pragma unroll
    for (int o = 1; o <= 2; o <<= 1) {
        m0 = fmaxf(m0, __shfl_xor_sync(FULLMASK, m0, o));
        m1 = fmaxf(m1, __shfl_xor_sync(FULLMASK, m1, o));
    }
    // padded output rows
    long r0 = (long)(blockIdx.x >> 5) * ERows + PADF
            + (blockIdx.x & 31) * 128 + wid * 16 + gid;
    long r1 = r0 + 8;
#pragma unroll
    for (int nt = 0; nt < 4; ++nt) {
        float2 e0, e1;
        e0.x = __expf(acc[nt][0] - m0); e0.y = __expf(acc[nt][1] - m0);
        e1.x = __expf(acc[nt][2] - m1); e1.y = __expf(acc[nt][3] - m1);
        *(float2*)&g_eexp[r0 * KK + nt * 8 + tig * 2] = e0;
        *(float2*)&g_eexp[r1 * KK + nt * 8 + tig * 2] = e1;
    }

    float msum = (tig == 0) ? (m0 + m1) : 0.f;
    msum = warpSum(msum);
    if (lane == 0) mred[wid] = msum;
    __syncthreads();
    if (tid == 0) {
        float s = 0.f;
#pragma unroll
        for (int i = 0; i < 8; ++i) s += mred[i];
        g_emaxpart[blockIdx.x] = s;
    }
}

// ---------------------------------------------------------------------------
// Kernel 3: tensor-core chunked scan. Warp = 16 chunks of one batch.
// U (16 chains x 32 states, bf16) x expA (32x32, bf16 B-frags) per step via
// 8 independent m16n8k16 MMAs; D-fragment layout == next step's A-fragment
// layout, so the recursion needs no shuffles. Renorm every 8 steps.
// ---------------------------------------------------------------------------
__global__ void __launch_bounds__(64) hmm_scan_kernel() {
    int w = blockIdx.x * 2 + (threadIdx.x >> 5);   // 0..255
    int lane = threadIdx.x & 31;
    int gid = lane >> 2, tig = lane & 3;
    int b = w >> 2;
    int g = w & 3;
    int c0 = g * 16 + gid;         // row gid's chunk   (never 63)
    int c1 = c0 + 8;               // row gid+8's chunk (never 0)
    const float* eb = g_eexp + (long)b * (ERows * KK);

    // B fragments from expA (row-major [j][n]); same convention as emission.
    uint32_t Bf[8][2];
#pragma unroll
    for (int ks = 0; ks < 2; ++ks)
#pragma unroll
        for (int nt = 0; nt < 4; ++nt) {
            int n = nt * 8 + gid;
            int r = ks * 16 + 2 * tig;
            Bf[ks * 4 + nt][0] = packbf2(g_expA[r * KK + n], g_expA[(r + 1) * KK + n]);
            Bf[ks * 4 + nt][1] = packbf2(g_expA[(r + 8) * KK + n], g_expA[(r + 9) * KK + n]);
        }

    // init packed state: c==0 -> pi * e(t=0); else all-ones
    uint32_t pk[4][2];
#pragma unroll
    for (int nt = 0; nt < 4; ++nt) {
        int col = nt * 8 + 2 * tig;
        float i00 = 1.f, i01 = 1.f;
        if (c0 == 0) {
            i00 = g_pi[col] * eb[PADF * KK + col];
            i01 = g_pi[col + 1] * eb[PADF * KK + col + 1];
        }
        pk[nt][0] = packbf2(i00, i01);
        pk[nt][1] = packbf2(1.f, 1.f);
    }

    int ilo0 = (c0 == 0) ? WARM : 0;                 // valid iff i >= ilo0
    int ihi1 = (c1 == CC - 1) ? (NSTEP - 1) : NSTEP; // valid iff i < ihi1

    const float* pe0 = eb + (long)(c0 * CHUNK + 1) * KK + 2 * tig;
    const float* pe1 = eb + (long)(c1 * CHUNK + 1) * KK + 2 * tig;

    float2 ring[4][8];             // [slot][row*4+nt], distance-4 prefetch
#pragma unroll
    for (int s = 0; s < 4; ++s)
#pragma unroll
        for (int nt = 0; nt < 4; ++nt) {
            ring[s][nt]     = *(const float2*)(pe0 + (long)s * KK + nt * 8);
            ring[s][4 + nt] = *(const float2*)(pe1 + (long)s * KK + nt * 8);
        }

    float logZ0 = 0.f, logZ1 = 0.f;
    for (int blk = 0; blk < NSTEP / 8; ++blk) {
        const float* q0 = pe0 + (long)(blk * 8 + 4) * KK;
        const float* q1 = pe1 + (long)(blk * 8 + 4) * KK;
        bool doLog = (blk >= WARM / 8);
#pragma unroll
        for (int ii = 0; ii < 8; ++ii) {
            int i = blk * 8 + ii;
            float dA[4][4], dB[4][4];
#pragma unroll
            for (int nt = 0; nt < 4; ++nt)
                mma_bf16_z(dA[nt], pk[0][0], pk[0][1], pk[1][0], pk[1][1],
                           Bf[nt][0], Bf[nt][1]);
#pragma unroll
            for (int nt = 0; nt < 4; ++nt)
                mma_bf16_z(dB[nt], pk[2][0], pk[2][1], pk[3][0], pk[3][1],
                           Bf[4 + nt][0], Bf[4 + nt][1]);

            const int slot = ii & 3;
            float v0[4][2], v1[4][2];
#pragma unroll
            for (int nt = 0; nt < 4; ++nt) {
                float2 e0 = ring[slot][nt];
                float2 e1 = ring[slot][4 + nt];
                v0[nt][0] = (dA[nt][0] + dB[nt][0]) * e0.x;
                v0[nt][1] = (dA[nt][1] + dB[nt][1]) * e0.y;
                v1[nt][0] = (dA[nt][2] + dB[nt][2]) * e1.x;
                v1[nt][1] = (dA[nt][3] + dB[nt][3]) * e1.y;
            }
            // refill this slot for step i+4 (reads stay inside padded array)
#pragma unroll
            for (int nt = 0; nt < 4; ++nt) {
                ring[slot][nt]     = *(const float2*)(q0 + (long)ii * KK + nt * 8);
                ring[slot][4 + nt] = *(const float2*)(q1 + (long)ii * KK + nt * 8);
            }

            bool val0 = (i >= ilo0);
            bool val1 = (i < ihi1);
            if (ii == 7) {             // block-end renorm
                float S0 = 0.f, S1 = 0.f;
#pragma unroll
                for (int nt = 0; nt < 4; ++nt) {
                    S0 += v0[nt][0] + v0[nt][1];
                    S1 += v1[nt][0] + v1[nt][1];
                }
#pragma unroll
                for (int o = 1; o <= 2; o <<= 1) {
                    S0 += __shfl_xor_sync(FULLMASK, S0, o);
                    S1 += __shfl_xor_sync(FULLMASK, S1, o);
                }
                bool ren0 = val0 && (doLog || c0 != 0);
                bool ren1 = val1;                      // c1 != 0 always
                float sc0 = ren0 ? __frcp_rn(S0) : 1.f;
                float sc1 = ren1 ? __frcp_rn(S1) : 1.f;
                if (doLog && val0) logZ0 += __logf(S0);
                if (doLog && val1) logZ1 += __logf(S1);
#pragma unroll
                for (int nt = 0; nt < 4; ++nt) {
                    v0[nt][0] *= sc0; v0[nt][1] *= sc0;
                    v1[nt][0] *= sc1; v1[nt][1] *= sc1;
                }
            }
#pragma unroll
            for (int nt = 0; nt < 4; ++nt) {
                uint32_t n0 = packbf2(v0[nt][0], v0[nt][1]);
                uint32_t n1 = packbf2(v1[nt][0], v1[nt][1]);
                pk[nt][0] = val0 ? n0 : pk[nt][0];
                pk[nt][1] = val1 ? n1 : pk[nt][1];
            }
        }
    }

    // final per-chain log from packed state
    float S0 = 0.f, S1 = 0.f;
#pragma unroll
    for (int nt = 0; nt < 4; ++nt) {
        __nv_bfloat162 h0 = *reinterpret_cast<__nv_bfloat162*>(&pk[nt][0]);
        __nv_bfloat162 h1 = *reinterpret_cast<__nv_bfloat162*>(&pk[nt][1]);
        S0 += __bfloat162float(h0.x) + __bfloat162float(h0.y);
        S1 += __bfloat162float(h1.x) + __bfloat162float(h1.y);
    }
#pragma unroll
    for (int o = 1; o <= 2; o <<= 1) {
        S0 += __shfl_xor_sync(FULLMASK, S0, o);
        S1 += __shfl_xor_sync(FULLMASK, S1, o);
    }
    if (tig == 0) {
        g_partial2[b * CC + c0] = logZ0 + __logf(S0);
        g_partial2[b * CC + c1] = logZ1 + __logf(S1);
    }
}

// ---------------------------------------------------------------------------
// Kernel 4: final scalar (deterministic fixed-order double reduction)
// ---------------------------------------------------------------------------
__global__ void __launch_bounds__(256) hmm_final_kernel(float* __restrict__ out) {
    __shared__ double red[8];
    int tid = threadIdx.x;
    double v = 0.0;
    const float4* p2 = (const float4*)g_partial2;
    const float4* pe = (const float4*)g_emaxpart;
#pragma unroll
    for (int i = tid; i < BB * CC / 4; i += 256) {
        float4 a = p2[i];
        v += (double)a.x + (double)a.y + (double)a.z + (double)a.w;
    }
#pragma unroll
    for (int i = tid; i < NEB / 4; i += 256) {
        float4 a = pe[i];
        v += (double)a.x + (double)a.y + (double)a.z + (double)a.w;
    }
#pragma unroll
    for (int o = 16; o > 0; o >>= 1) v += __shfl_xor_sync(FULLMASK, v, o);
    if ((tid & 31) == 0) red[tid >> 5] = v;
    __syncthreads();
    if (tid < 8) {
        double wv = red[tid];
#pragma unroll
        for (int o = 4; o > 0; o >>= 1) wv += __shfl_xor_sync(0xff, wv, o);
        if (tid == 0) out[0] = (float)wv;
    }
}

// ---------------------------------------------------------------------------
extern "C" void kernel_launch(void* const* d_in, const int* in_sizes, int n_in,
                              void* d_out, int out_size) {
    const float* X = (const float*)d_in[0];
    const float* sp = (const float*)d_in[1];
    const float* trans = (const float*)d_in[2];
    const float* mu = (const float*)d_in[3];
    const float* log_var = (const float*)d_in[4];

    hmm_prep_kernel<<<8, 256>>>(sp, trans, mu, log_var);
    hmm_emis_kernel<<<NEB, 256>>>(X);
    hmm_scan_kernel<<<BB * CC / 32, 64>>>();
    hmm_final_kernel<<<1, 256>>>((float*)d_out);
}

// round 10
// speedup vs baseline: 2.4108x; 1.3327x over previous
#include <cuda_runtime.h>
#include <cuda_bf16.h>
#include <math.h>
#include <stdint.h>

#define BB 64
#define TT 4096
#define DD 90
#define KK 32
#define CC 128           // chunks per batch
#define CHUNK 32         // TT / CC
#define WARM 16          // burn-in steps (contraction 0.46^16 ~ 4e-6 per chunk)
#define NSTEP (WARM + CHUNK)     // 48
#define PADF 16          // MUST == WARM (scan reads rows without +PADF -> -WARM shift)
#define PADB 8
#define ERows (PADF + TT + PADB) // 4120 rows per batch
#define NEB (BB * TT / 128)      // 2048 emission blocks
#define LOG2PI_F 1.8378770664093453f
#define FULLMASK 0xffffffffu

// ---- scratch (__device__ globals; no allocations allowed) ----
__device__ __align__(16) __nv_bfloat16 g_ee16[BB * ERows * KK]; // exp(em-emax), bf16, col-permuted
__device__ __align__(16) uint2 g_Wb[12 * 4 * 32];        // bf16 B-fragment table
__device__ __align__(16) float g_bias[KK];
__device__ float g_pi[KK];
__device__ float g_expA[KK * KK];
__device__ __align__(16) float g_partial2[BB * CC];      // 8192 per-chunk log factors
__device__ __align__(16) float g_emaxpart[NEB];          // per-emis-block emax sums

__device__ __forceinline__ float warpMax(float v) {
#pragma unroll
    for (int o = 16; o > 0; o >>= 1) v = fmaxf(v, __shfl_xor_sync(FULLMASK, v, o));
    return v;
}
__device__ __forceinline__ float warpSum(float v) {
#pragma unroll
    for (int o = 16; o > 0; o >>= 1) v += __shfl_xor_sync(FULLMASK, v, o);
    return v;
}
__device__ __forceinline__ uint32_t packbf2(float lo, float hi) {
    __nv_bfloat162 h = __floats2bfloat162_rn(lo, hi);
    return *reinterpret_cast<uint32_t*>(&h);
}
__device__ __forceinline__ __nv_bfloat162 bfu(uint32_t v) {
    return *reinterpret_cast<__nv_bfloat162*>(&v);
}
__device__ __forceinline__ uint32_t ubf(__nv_bfloat162 h) {
    return *reinterpret_cast<uint32_t*>(&h);
}
__device__ __forceinline__ void mma_bf16(float& d0, float& d1, float& d2, float& d3,
                                         uint32_t a0, uint32_t a1, uint32_t a2, uint32_t a3,
                                         uint32_t b0, uint32_t b1) {
    asm volatile("mma.sync.aligned.m16n8k16.row.col.f32.bf16.bf16.f32 "
                 "{%0,%1,%2,%3},{%4,%5,%6,%7},{%8,%9},{%0,%1,%2,%3};"
                 : "+f"(d0), "+f"(d1), "+f"(d2), "+f"(d3)
                 : "r"(a0), "r"(a1), "r"(a2), "r"(a3), "r"(b0), "r"(b1));
}
__device__ __forceinline__ void mma_bf16_z(float* d,
                                           uint32_t a0, uint32_t a1, uint32_t a2, uint32_t a3,
                                           uint32_t b0, uint32_t b1) {
    asm volatile("mma.sync.aligned.m16n8k16.row.col.f32.bf16.bf16.f32 "
                 "{%0,%1,%2,%3},{%4,%5,%6,%7},{%8,%9},{%10,%10,%10,%10};"
                 : "=f"(d[0]), "=f"(d[1]), "=f"(d[2]), "=f"(d[3])
                 : "r"(a0), "r"(a1), "r"(a2), "r"(a3), "r"(b0), "r"(b1), "f"(0.0f));
}

// ---------------------------------------------------------------------------
// Kernel 1: prep — grid 8 x 256. Triggers PDL immediately so emission can
// launch and stage X concurrently.
// ---------------------------------------------------------------------------
__global__ void __launch_bounds__(256) hmm_prep_kernel(
        const float* __restrict__ sp, const float* __restrict__ trans,
        const float* __restrict__ mu, const float* __restrict__ log_var) {
    cudaTriggerProgrammaticLaunchCompletion();
    int tid = threadIdx.x, wid = tid >> 5, lane = tid & 31;
    int gw = blockIdx.x * 8 + wid;

    if (gw < 32) {
        float v = trans[gw * KK + lane];
        float m = warpMax(v);
        float e = expf(v - m);
        float s = warpSum(e);
        g_expA[gw * KK + lane] = e / s;
        if (gw == 0) {
            float pv = sp[lane];
            float pm = warpMax(pv);
            float pe = expf(pv - pm);
            float ps = warpSum(pe);
            g_pi[lane] = pe / ps;
        }
    } else {
        int k = gw - 32;
        float acc = 0.0f;
        for (int d = lane; d < DD; d += 32) {
            float lv = log_var[k * DD + d];
            float iv = expf(-lv);
            float m = mu[k * DD + d];
            acc = fmaf(m * m, iv, acc + lv);
        }
        acc = warpSum(acc);
        if (lane == 0) g_bias[k] = -0.5f * (acc + (float)DD * LOG2PI_F);
    }

    int p = blockIdx.x * 256 + tid;
    if (p < 12 * 4 * 32) {
        int s = p >> 7;
        int rem = p & 127;
        int ln = rem & 31;
        int gid = ln >> 2, tig = ln & 3;
        int n = (rem >> 5) * 8 + gid;
        float w[4];
#pragma unroll
        for (int h = 0; h < 4; ++h) {
            int row = s * 16 + tig * 2 + (h >> 1) * 8 + (h & 1);
            float v = 0.f;
            if (row < 96) {
                int d = row;
                if (d < DD) v = mu[n * DD + d] * expf(-log_var[n * DD + d]);
            } else {
                int d = row - 96;
                if (d < DD) v = -0.5f * expf(-log_var[n * DD + d]);
            }
            w[h] = v;
        }
        g_Wb[p] = make_uint2(packbf2(w[0], w[1]), packbf2(w[2], w[3]));
    }
}

// ---------------------------------------------------------------------------
// Kernel 2: emissions via bf16 m16n8k16 tensor cores, PDL-overlapped with
// prep (X staged before the dependency sync). Output bf16, column-permuted
// (storage col = tig*8 + nt*2 + h for logical n = nt*8 + tig*2 + h) so each
// row-thread stores one uint4 and the scan loads one LDG.128 per row.
// ---------------------------------------------------------------------------
__global__ void __launch_bounds__(256) hmm_emis_kernel(const float* __restrict__ X) {
    cudaTriggerProgrammaticLaunchCompletion();
    __shared__ __align__(16) float xs[128 * DD];       // 46.08 KB
    __shared__ __align__(16) uint2 ws[12 * 4 * 32];    // 12 KB
    __shared__ __align__(8) float sbias[KK];
    __shared__ float mred[8];

    int tid = threadIdx.x;
    int wid = tid >> 5, lane = tid & 31;
    int gid = lane >> 2, tig = lane & 3;

    {   // stage X tile first — independent of prep
        const float4* X4 = (const float4*)(X + (long)blockIdx.x * 128 * DD);
        float4* xs4 = (float4*)xs;
#pragma unroll
        for (int i = 0; i < 11; ++i) xs4[tid + 256 * i] = X4[tid + 256 * i];
        if (tid < 2880 - 2816) xs4[tid + 2816] = X4[tid + 2816];
    }
    cudaGridDependencySynchronize();     // wait for prep's g_Wb / g_bias
    {
        const uint4* src = (const uint4*)g_Wb;
        uint4* dst = (uint4*)ws;
#pragma unroll
        for (int i = 0; i < 3; ++i) dst[tid + 256 * i] = src[tid + 256 * i];
        if (tid < KK) sbias[tid] = g_bias[tid];
    }
    __syncthreads();

    const float* xr0 = xs + (wid * 16 + gid) * DD;
    const float* xr1 = xr0 + 8 * DD;

    float acc[4][4];
#pragma unroll
    for (int nt = 0; nt < 4; ++nt)
#pragma unroll
        for (int i = 0; i < 4; ++i) acc[nt][i] = 0.f;

#pragma unroll
    for (int s = 0; s < 6; ++s) {
        int c0 = s * 16 + tig * 2;
        int c1 = c0 + 8;
        float2 z = make_float2(0.f, 0.f);
        float2 f00 = (c0 < DD) ? *(const float2*)(xr0 + c0) : z;
        float2 f10 = (c0 < DD) ? *(const float2*)(xr1 + c0) : z;
        float2 f01 = (c1 < DD) ? *(const float2*)(xr0 + c1) : z;
        float2 f11 = (c1 < DD) ? *(const float2*)(xr1 + c1) : z;
        uint32_t a0 = packbf2(f00.x, f00.y), a1 = packbf2(f10.x, f10.y);
        uint32_t a2 = packbf2(f01.x, f01.y), a3 = packbf2(f11.x, f11.y);
        uint32_t q0 = packbf2(f00.x * f00.x, f00.y * f00.y);
        uint32_t q1 = packbf2(f10.x * f10.x, f10.y * f10.y);
        uint32_t q2 = packbf2(f01.x * f01.x, f01.y * f01.y);
        uint32_t q3 = packbf2(f11.x * f11.x, f11.y * f11.y);
#pragma unroll
        for (int nt = 0; nt < 4; ++nt) {
            uint2 bb = ws[(s * 4 + nt) * 32 + lane];
            mma_bf16(acc[nt][0], acc[nt][1], acc[nt][2], acc[nt][3],
                     a0, a1, a2, a3, bb.x, bb.y);
        }
#pragma unroll
        for (int nt = 0; nt < 4; ++nt) {
            uint2 bb = ws[((s + 6) * 4 + nt) * 32 + lane];
            mma_bf16(acc[nt][0], acc[nt][1], acc[nt][2], acc[nt][3],
                     q0, q1, q2, q3, bb.x, bb.y);
        }
    }

    const float2* sb2 = (const float2*)sbias;
    float m0 = -1e30f, m1 = -1e30f;
#pragma unroll
    for (int nt = 0; nt < 4; ++nt) {
        float2 bv = sb2[nt * 4 + tig];
        acc[nt][0] += bv.x; acc[nt][1] += bv.y;
        acc[nt][2] += bv.x; acc[nt][3] += bv.y;
        m0 = fmaxf(m0, fmaxf(acc[nt][0], acc[nt][1]));
        m1 = fmaxf(m1, fmaxf(acc[nt][2], acc[nt][3]));
    }
#pragma unroll
    for (int o = 1; o <= 2; o <<= 1) {
        m0 = fmaxf(m0, __shfl_xor_sync(FULLMASK, m0, o));
        m1 = fmaxf(m1, __shfl_xor_sync(FULLMASK, m1, o));
    }
    long r0 = (long)(blockIdx.x >> 5) * ERows + PADF
            + (blockIdx.x & 31) * 128 + wid * 16 + gid;
    long r1 = r0 + 8;
    uint4 o0, o1;
    o0.x = packbf2(__expf(acc[0][0] - m0), __expf(acc[0][1] - m0));
    o0.y = packbf2(__expf(acc[1][0] - m0), __expf(acc[1][1] - m0));
    o0.z = packbf2(__expf(acc[2][0] - m0), __expf(acc[2][1] - m0));
    o0.w = packbf2(__expf(acc[3][0] - m0), __expf(acc[3][1] - m0));
    o1.x = packbf2(__expf(acc[0][2] - m1), __expf(acc[0][3] - m1));
    o1.y = packbf2(__expf(acc[1][2] - m1), __expf(acc[1][3] - m1));
    o1.z = packbf2(__expf(acc[2][2] - m1), __expf(acc[2][3] - m1));
    o1.w = packbf2(__expf(acc[3][2] - m1), __expf(acc[3][3] - m1));
    ((uint4*)(g_ee16 + r0 * KK))[tig] = o0;
    ((uint4*)(g_ee16 + r1 * KK))[tig] = o1;

    float msum = (tig == 0) ? (m0 + m1) : 0.f;
    msum = warpSum(msum);
    if (lane == 0) mred[wid] = msum;
    __syncthreads();
    if (tid == 0) {
        float s = 0.f;
#pragma unroll
        for (int i = 0; i < 8; ++i) s += mred[i];
        g_emaxpart[blockIdx.x] = s;
    }
}

// ---------------------------------------------------------------------------
// Kernel 3: tensor-core chunked scan, CC=128 (48 serial steps), 4 warps/block,
// 128 blocks. Rows read WITHOUT +PADF: since PADF==WARM this implements the
// burn-in window [c*CHUNK-WARM+1, c*CHUNK] then useful [c*CHUNK+1,(c+1)*CHUNK].
// ---------------------------------------------------------------------------
__global__ void __launch_bounds__(128) hmm_scan_kernel() {
    cudaTriggerProgrammaticLaunchCompletion();
    cudaGridDependencySynchronize();     // wait for emission (and transitively prep)
    int wid = threadIdx.x >> 5;
    int w = blockIdx.x * 4 + wid;        // 0..511
    int lane = threadIdx.x & 31;
    int gid = lane >> 2, tig = lane & 3;
    int b = w >> 3;                      // 8 warps per batch
    int g = w & 7;
    int c0 = g * 16 + gid;               // 0..119 (==0 only for g==0,gid==0)
    int c1 = c0 + 8;                     // 8..127
    const __nv_bfloat16* eb = g_ee16 + (long)b * (ERows * KK);

    // B fragments from expA (same convention validated in R9)
    uint32_t Bf[8][2];
#pragma unroll
    for (int ks = 0; ks < 2; ++ks)
#pragma unroll
        for (int nt = 0; nt < 4; ++nt) {
            int n = nt * 8 + gid;
            int r = ks * 16 + 2 * tig;
            Bf[ks * 4 + nt][0] = packbf2(g_expA[r * KK + n], g_expA[(r + 1) * KK + n]);
            Bf[ks * 4 + nt][1] = packbf2(g_expA[(r + 8) * KK + n], g_expA[(r + 9) * KK + n]);
        }

    // init packed state: c==0 -> pi * e(t=0) (row PADF); else ones
    uint32_t pk[4][2];
    {
        uint4 ei = ((const uint4*)(eb + (long)PADF * KK))[tig];
        uint32_t ec[4] = {ei.x, ei.y, ei.z, ei.w};
#pragma unroll
        for (int nt = 0; nt < 4; ++nt) {
            float i00 = 1.f, i01 = 1.f;
            if (c0 == 0) {
                float2 ef = __bfloat1622float2(bfu(ec[nt]));
                i00 = g_pi[nt * 8 + 2 * tig] * ef.x;
                i01 = g_pi[nt * 8 + 2 * tig + 1] * ef.y;
            }
            pk[nt][0] = packbf2(i00, i01);
            pk[nt][1] = packbf2(1.f, 1.f);
        }
    }

    int ilo0 = (c0 == 0) ? WARM : 0;                 // row0 valid iff i >= ilo0
    int ihi1 = (c1 == CC - 1) ? (NSTEP - 1) : NSTEP; // row1 valid iff i < ihi1

    const __nv_bfloat16* pe0 = eb + (long)(c0 * CHUNK + 1) * KK;
    const __nv_bfloat16* pe1 = eb + (long)(c1 * CHUNK + 1) * KK;

    uint4 ring0[4], ring1[4];            // distance-4 prefetch
#pragma unroll
    for (int s = 0; s < 4; ++s) {
        ring0[s] = ((const uint4*)(pe0 + (long)s * KK))[tig];
        ring1[s] = ((const uint4*)(pe1 + (long)s * KK))[tig];
    }

    float logZ0 = 0.f, logZ1 = 0.f;
    for (int blk = 0; blk < NSTEP / 8; ++blk) {      // 6 blocks
        const __nv_bfloat16* q0 = pe0 + (long)(blk * 8 + 4) * KK;
        const __nv_bfloat16* q1 = pe1 + (long)(blk * 8 + 4) * KK;
        bool doLog = (blk >= WARM / 8);
#pragma unroll
        for (int ii = 0; ii < 8; ++ii) {
            int i = blk * 8 + ii;
            float dA[4][4], dB[4][4];
#pragma unroll
            for (int nt = 0; nt < 4; ++nt)
                mma_bf16_z(dA[nt], pk[0][0], pk[0][1], pk[1][0], pk[1][1],
                           Bf[nt][0], Bf[nt][1]);
#pragma unroll
            for (int nt = 0; nt < 4; ++nt)
                mma_bf16_z(dB[nt], pk[2][0], pk[2][1], pk[3][0], pk[3][1],
                           Bf[4 + nt][0], Bf[4 + nt][1]);

            const int slot = ii & 3;
            uint4 e0 = ring0[slot], e1 = ring1[slot];
            ring0[slot] = ((const uint4*)(q0 + (long)ii * KK))[tig];
            ring1[slot] = ((const uint4*)(q1 + (long)ii * KK))[tig];
            uint32_t ec0[4] = {e0.x, e0.y, e0.z, e0.w};
            uint32_t ec1[4] = {e1.x, e1.y, e1.z, e1.w};

            __nv_bfloat162 n0[4], n1[4];
#pragma unroll
            for (int nt = 0; nt < 4; ++nt) {
                __nv_bfloat162 d0 = __floats2bfloat162_rn(dA[nt][0] + dB[nt][0],
                                                          dA[nt][1] + dB[nt][1]);
                __nv_bfloat162 d1 = __floats2bfloat162_rn(dA[nt][2] + dB[nt][2],
                                                          dA[nt][3] + dB[nt][3]);
                n0[nt] = __hmul2(d0, bfu(ec0[nt]));
                n1[nt] = __hmul2(d1, bfu(ec1[nt]));
            }

            bool val0 = (i >= ilo0);
            bool val1 = (i < ihi1);
            if (ii == 7) {               // block-end renorm
                float S0 = 0.f, S1 = 0.f;
#pragma unroll
                for (int nt = 0; nt < 4; ++nt) {
                    float2 a = __bfloat1622float2(n0[nt]);
                    float2 c = __bfloat1622float2(n1[nt]);
                    S0 += a.x + a.y;
                    S1 += c.x + c.y;
                }
#pragma unroll
                for (int o = 1; o <= 2; o <<= 1) {
                    S0 += __shfl_xor_sync(FULLMASK, S0, o);
                    S1 += __shfl_xor_sync(FULLMASK, S1, o);
                }
                bool ren0 = val0 && (doLog || c0 != 0);
                bool ren1 = val1;
                float sc0 = ren0 ? __frcp_rn(S0) : 1.f;
                float sc1 = ren1 ? __frcp_rn(S1) : 1.f;
                if (doLog && val0) logZ0 += __logf(S0);
                if (doLog && val1) logZ1 += __logf(S1);
                __nv_bfloat162 sb0 = __float2bfloat162_rn(sc0);
                __nv_bfloat162 sb1 = __float2bfloat162_rn(sc1);
#pragma unroll
                for (int nt = 0; nt < 4; ++nt) {
                    n0[nt] = __hmul2(n0[nt], sb0);
                    n1[nt] = __hmul2(n1[nt], sb1);
                }
            }
#pragma unroll
            for (int nt = 0; nt < 4; ++nt) {
                pk[nt][0] = val0 ? ubf(n0[nt]) : pk[nt][0];
                pk[nt][1] = val1 ? ubf(n1[nt]) : pk[nt][1];
            }
        }
    }

    float S0 = 0.f, S1 = 0.f;
#pragma unroll
    for (int nt = 0; nt < 4; ++nt) {
        float2 a = __bfloat1622float2(bfu(pk[nt][0]));
        float2 c = __bfloat1622float2(bfu(pk[nt][1]));
        S0 += a.x + a.y;
        S1 += c.x + c.y;
    }
#pragma unroll
    for (int o = 1; o <= 2; o <<= 1) {
        S0 += __shfl_xor_sync(FULLMASK, S0, o);
        S1 += __shfl_xor_sync(FULLMASK, S1, o);
    }
    if (tig == 0) {
        g_partial2[b * CC + c0] = logZ0 + __logf(S0);
        g_partial2[b * CC + c1] = logZ1 + __logf(S1);
    }
}

// ---------------------------------------------------------------------------
// Kernel 4: final scalar (deterministic fixed-order double reduction)
// ---------------------------------------------------------------------------
__global__ void __launch_bounds__(256) hmm_final_kernel(float* __restrict__ out) {
    cudaGridDependencySynchronize();
    __shared__ double red[8];
    int tid = threadIdx.x;
    double v = 0.0;
    const float4* p2 = (const float4*)g_partial2;
    const float4* pe = (const float4*)g_emaxpart;
#pragma unroll
    for (int i = tid; i < BB * CC / 4; i += 256) {
        float4 a = p2[i];
        v += (double)a.x + (double)a.y + (double)a.z + (double)a.w;
    }
#pragma unroll
    for (int i = tid; i < NEB / 4; i += 256) {
        float4 a = pe[i];
        v += (double)a.x + (double)a.y + (double)a.z + (double)a.w;
    }
#pragma unroll
    for (int o = 16; o > 0; o >>= 1) v += __shfl_xor_sync(FULLMASK, v, o);
    if ((tid & 31) == 0) red[tid >> 5] = v;
    __syncthreads();
    if (tid < 8) {
        double wv = red[tid];
#pragma unroll
        for (int o = 4; o > 0; o >>= 1) wv += __shfl_xor_sync(0xff, wv, o);
        if (tid == 0) out[0] = (float)wv;
    }
}

// ---------------------------------------------------------------------------
extern "C" void kernel_launch(void* const* d_in, const int* in_sizes, int n_in,
                              void* d_out, int out_size) {
    const float* X = (const float*)d_in[0];
    const float* sp = (const float*)d_in[1];
    const float* trans = (const float*)d_in[2];
    const float* mu = (const float*)d_in[3];
    const float* log_var = (const float*)d_in[4];

    hmm_prep_kernel<<<8, 256>>>(sp, trans, mu, log_var);

    cudaLaunchAttribute at[1];
    at[0].id = cudaLaunchAttributeProgrammaticStreamSerialization;
    at[0].val.programmaticStreamSerializationAllowed = 1;

    cudaLaunchConfig_t cfg = {};
    cfg.attrs = at;
    cfg.numAttrs = 1;
    cfg.stream = 0;

    cfg.gridDim = dim3(NEB);
    cfg.blockDim = dim3(256);
    cudaLaunchKernelEx(&cfg, hmm_emis_kernel, X);

    cfg.gridDim = dim3(BB * CC / 64);   // 128 blocks x 4 warps
    cfg.blockDim = dim3(128);
    cudaLaunchKernelEx(&cfg, hmm_scan_kernel);

    cfg.gridDim = dim3(1);
    cfg.blockDim = dim3(256);
    float* outp = (float*)d_out;
    cudaLaunchKernelEx(&cfg, hmm_final_kernel, outp);
}